// round 5
// baseline (speedup 1.0000x reference)
#include <cuda_runtime.h>
#include <cstdint>
#include <math.h>

#define IN_SIZE  128
#define OUT_SIZE 128
#define BATCH    1024
#define N_SUB    (IN_SIZE * OUT_SIZE)

// Per-subnet table: [0..7] sorted thresholds | [8..151] 9 intervals x (a0,b0..a7,b7)
//                   [152..159] w3 | [160] b3 | [161..167] pad   => 168 floats
#define TAB_STRIDE 168

__device__ float g_xT[IN_SIZE * BATCH];            // transposed x
__device__ float g_tab[N_SUB * TAB_STRIDE];        // 11 MB scratch, static

// ---------------- zero the output (it is poisoned before timing) ----------------
__global__ void zero_out_kernel(float* __restrict__ out) {
    reinterpret_cast<float4*>(out)[blockIdx.x * 256 + threadIdx.x] =
        make_float4(0.f, 0.f, 0.f, 0.f);
}

// ---------------- transpose x [B,128] -> xT [128,B] ----------------
__global__ void xt_kernel(const float* __restrict__ x) {
    __shared__ float t[32][33];
    const int i0 = blockIdx.x * 32;
    const int bx = blockIdx.y * 32;
    const int tx = threadIdx.x, ty = threadIdx.y;  // 32 x 8
#pragma unroll
    for (int r = 0; r < 32; r += 8)
        t[ty + r][tx] = x[(bx + ty + r) * IN_SIZE + i0 + tx];
    __syncthreads();
#pragma unroll
    for (int r = 0; r < 32; r += 8)
        g_xT[(i0 + ty + r) * BATCH + bx + tx] = t[tx][ty + r];
}

// ---------------- precompute: exact per-interval linearization ----------------
// For x in interval s, layer-2 pre-activation z_j = a_{j,s} x + b_{j,s} exactly
// (masks of layer-1 relus are constant within an interval).
__global__ void prep_kernel(const float* __restrict__ W1, const float* __restrict__ b1,
                            const float* __restrict__ W2, const float* __restrict__ b2,
                            const float* __restrict__ W3, const float* __restrict__ b3) {
    const int n = blockIdx.x * 128 + threadIdx.x;

    float w1[8], c1[8], w2[64], c2[8];
#pragma unroll
    for (int k = 0; k < 8; k++) {
        w1[k] = W1[n * 8 + k];
        c1[k] = b1[n * 8 + k];
        c2[k] = b2[n * 8 + k];
    }
#pragma unroll
    for (int e = 0; e < 64; e++) w2[e] = W2[n * 64 + e];

    // thresholds (guard w1==0 / inf / NaN with +1e38 sentinel; mask at the
    // representative point handles the constant-hinge case correctly)
    float t[8];
#pragma unroll
    for (int k = 0; k < 8; k++) {
        float v = -c1[k] / w1[k];
        if (!(fabsf(v) <= 1e38f)) v = 1e38f;
        t[k] = v;
    }
    // odd-even transposition sort (fully unrolled, register-resident)
#pragma unroll
    for (int p = 0; p < 8; p++) {
#pragma unroll
        for (int k = 0; k < 7; k++) {
            if ((k & 1) == (p & 1)) {
                float lo = fminf(t[k], t[k + 1]);
                float hi = fmaxf(t[k], t[k + 1]);
                t[k] = lo; t[k + 1] = hi;
            }
        }
    }

    float* dst = g_tab + (size_t)n * TAB_STRIDE;
#pragma unroll
    for (int k = 0; k < 8; k++) dst[k] = t[k];

#pragma unroll
    for (int s = 0; s < 9; s++) {
        // representative point strictly inside interval s (robust offsets at ends)
        float rep;
        if (s == 0)       rep = t[0] - (1.0f + 0.5f * fabsf(t[0]));
        else if (s == 8)  rep = t[7] + (1.0f + 0.5f * fabsf(t[7]));
        else              rep = 0.5f * t[s - 1] + 0.5f * t[s];

        float mw[8], mb[8];
#pragma unroll
        for (int k = 0; k < 8; k++) {
            const bool act = fmaf(w1[k], rep, c1[k]) > 0.0f;
            mw[k] = act ? w1[k] : 0.0f;
            mb[k] = act ? c1[k] : 0.0f;
        }
#pragma unroll
        for (int j = 0; j < 8; j++) {
            float a = 0.0f, b = c2[j];
#pragma unroll
            for (int k = 0; k < 8; k++) {
                a = fmaf(w2[j * 8 + k], mw[k], a);
                b = fmaf(w2[j * 8 + k], mb[k], b);
            }
            dst[8 + s * 16 + j * 2]     = a;
            dst[8 + s * 16 + j * 2 + 1] = b;
        }
    }
#pragma unroll
    for (int k = 0; k < 8; k++) dst[152 + k] = W3[n * 8 + k];
    dst[160] = b3[n];
}

// ---------------- eval: per (n,b) = interval lookup + 8 hinges ----------------
#define I_PER_CTA 32
#define SMEM_BYTES (I_PER_CTA * TAB_STRIDE * 4)  // 21504

__device__ __forceinline__ float eval_one(
    float xe, const float* __restrict__ sb,
    float t0, float t1, float t2, float t3,
    float t4, float t5, float t6, float t7,
    float4 w3a, float4 w3b, float b3v) {
    int c = (xe > t0);
    c += (xe > t1); c += (xe > t2); c += (xe > t3);
    c += (xe > t4); c += (xe > t5); c += (xe > t6); c += (xe > t7);
    const float4* g = reinterpret_cast<const float4*>(sb + 8 + c * 16);
    const float4 p0 = g[0], p1 = g[1], p2 = g[2], p3 = g[3];
    float s = b3v;
    s = fmaf(w3a.x, fmaxf(fmaf(p0.x, xe, p0.y), 0.f), s);
    s = fmaf(w3a.y, fmaxf(fmaf(p0.z, xe, p0.w), 0.f), s);
    s = fmaf(w3a.z, fmaxf(fmaf(p1.x, xe, p1.y), 0.f), s);
    s = fmaf(w3a.w, fmaxf(fmaf(p1.z, xe, p1.w), 0.f), s);
    s = fmaf(w3b.x, fmaxf(fmaf(p2.x, xe, p2.y), 0.f), s);
    s = fmaf(w3b.y, fmaxf(fmaf(p2.z, xe, p2.w), 0.f), s);
    s = fmaf(w3b.z, fmaxf(fmaf(p3.x, xe, p3.y), 0.f), s);
    s = fmaf(w3b.w, fmaxf(fmaf(p3.z, xe, p3.w), 0.f), s);
    return s;
}

__global__ void __launch_bounds__(128, 4) eval_kernel(float* __restrict__ out) {
    extern __shared__ float sw[];
    const int o     = blockIdx.x;
    const int bt    = blockIdx.y;
    const int ibase = blockIdx.z * I_PER_CTA;
    const int tid   = threadIdx.x;

    // Stage 32 subnet tables (coalesced float4 copy, 42 float4 per table)
    for (int idx = tid; idx < I_PER_CTA * 42; idx += 128) {
        const int li = idx / 42;
        const int e  = idx - li * 42;
        const int n  = ((ibase + li) << 7) | o;
        reinterpret_cast<float4*>(sw)[li * 42 + e] =
            __ldg(reinterpret_cast<const float4*>(g_tab +
                                                  (size_t)n * TAB_STRIDE) + e);
    }
    __syncthreads();

    const int b0 = bt * 512 + tid * 4;
    float4 xv = __ldg(reinterpret_cast<const float4*>(g_xT + ibase * BATCH + b0));

    float acc0 = 0.f, acc1 = 0.f, acc2 = 0.f, acc3 = 0.f;

    for (int li = 0; li < I_PER_CTA; li++) {
        const int inx = ibase + ((li < I_PER_CTA - 1) ? (li + 1) : li);
        const float4 xnext =
            __ldg(reinterpret_cast<const float4*>(g_xT + inx * BATCH + b0));

        const float* sb = sw + li * TAB_STRIDE;
        const float4 tq0 = *reinterpret_cast<const float4*>(sb);
        const float4 tq1 = *reinterpret_cast<const float4*>(sb + 4);
        const float4 w3a = *reinterpret_cast<const float4*>(sb + 152);
        const float4 w3b = *reinterpret_cast<const float4*>(sb + 156);
        const float  b3v = sb[160];

        acc0 += eval_one(xv.x, sb, tq0.x, tq0.y, tq0.z, tq0.w,
                         tq1.x, tq1.y, tq1.z, tq1.w, w3a, w3b, b3v);
        acc1 += eval_one(xv.y, sb, tq0.x, tq0.y, tq0.z, tq0.w,
                         tq1.x, tq1.y, tq1.z, tq1.w, w3a, w3b, b3v);
        acc2 += eval_one(xv.z, sb, tq0.x, tq0.y, tq0.z, tq0.w,
                         tq1.x, tq1.y, tq1.z, tq1.w, w3a, w3b, b3v);
        acc3 += eval_one(xv.w, sb, tq0.x, tq0.y, tq0.z, tq0.w,
                         tq1.x, tq1.y, tq1.z, tq1.w, w3a, w3b, b3v);

        xv = xnext;
    }

    atomicAdd(&out[(b0 + 0) * OUT_SIZE + o], acc0);
    atomicAdd(&out[(b0 + 1) * OUT_SIZE + o], acc1);
    atomicAdd(&out[(b0 + 2) * OUT_SIZE + o], acc2);
    atomicAdd(&out[(b0 + 3) * OUT_SIZE + o], acc3);
}

extern "C" void kernel_launch(void* const* d_in, const int* in_sizes, int n_in,
                              void* d_out, int out_size) {
    const float* x  = (const float*)d_in[0];
    const float* W1 = (const float*)d_in[1];
    const float* b1 = (const float*)d_in[2];
    const float* W2 = (const float*)d_in[3];
    const float* b2 = (const float*)d_in[4];
    const float* W3 = (const float*)d_in[5];
    const float* b3 = (const float*)d_in[6];
    float* out = (float*)d_out;

    cudaFuncSetAttribute(eval_kernel, cudaFuncAttributeMaxDynamicSharedMemorySize,
                         SMEM_BYTES);

    zero_out_kernel<<<BATCH * OUT_SIZE / (256 * 4), 256>>>(out);
    xt_kernel<<<dim3(IN_SIZE / 32, BATCH / 32), dim3(32, 8)>>>(x);
    prep_kernel<<<N_SUB / 128, 128>>>(W1, b1, W2, b2, W3, b3);
    eval_kernel<<<dim3(OUT_SIZE, 2, 4), 128, SMEM_BYTES>>>(out);
}

// round 6
// speedup vs baseline: 1.7044x; 1.7044x over previous
#include <cuda_runtime.h>
#include <cstdint>
#include <math.h>

#define IN_SIZE  128
#define OUT_SIZE 128
#define BATCH    1024
#define N_SUB    (IN_SIZE * OUT_SIZE)

// Per-subnet table (200 floats, 800B):
//  [0..7]    sorted thresholds
//  [8+20s .. 8+20s+15]  interval s (s=0..8): 8 x (a_j, b_j)   (stride 20 = 80B
//            => distinct starting bank-quads for all intervals except c0/c8)
//  [188..195] w3   [196] b3   [197..199] pad
#define TAB 200

__device__ float g_xT[IN_SIZE * BATCH];       // transposed x
__device__ float g_tab[N_SUB * TAB];          // 13.1 MB static scratch

// ---------------- transpose x [B,128] -> xT [128,B] ----------------
__global__ void xt_kernel(const float* __restrict__ x) {
    __shared__ float t[32][33];
    const int i0 = blockIdx.x * 32;
    const int bx = blockIdx.y * 32;
    const int tx = threadIdx.x, ty = threadIdx.y;  // 32 x 8
#pragma unroll
    for (int r = 0; r < 32; r += 8)
        t[ty + r][tx] = x[(bx + ty + r) * IN_SIZE + i0 + tx];
    __syncthreads();
#pragma unroll
    for (int r = 0; r < 32; r += 8)
        g_xT[(i0 + ty + r) * BATCH + bx + tx] = t[tx][ty + r];
}

// ---------------- prep: exact per-interval linearization (8 lanes/subnet) ----
// Lane j of each 8-lane group handles hidden unit j of subnet n.
// Also zeroes the output buffer (it is poisoned before timing).
__global__ void prep_kernel(const float* __restrict__ W1, const float* __restrict__ b1,
                            const float* __restrict__ W2, const float* __restrict__ b2,
                            const float* __restrict__ W3, const float* __restrict__ b3,
                            float* __restrict__ out) {
    const int gid = blockIdx.x * 256 + threadIdx.x;      // 131072 threads
    if (gid < BATCH * OUT_SIZE / 4)                       // zero out (32768 f4)
        reinterpret_cast<float4*>(out)[gid] = make_float4(0.f, 0.f, 0.f, 0.f);

    const int n = gid >> 3;
    const int j = gid & 7;

    float w1[8], c1[8], w2r[8];
#pragma unroll
    for (int k = 0; k < 8; k++) {
        w1[k]  = __ldg(W1 + n * 8 + k);
        c1[k]  = __ldg(b1 + n * 8 + k);
        w2r[k] = __ldg(W2 + n * 64 + j * 8 + k);
    }
    const float c2j = __ldg(b2 + n * 8 + j);

    // thresholds (sentinel 1e38 for w1==0 / non-finite); sorted (redundant/lane)
    float t[8];
#pragma unroll
    for (int k = 0; k < 8; k++) {
        float v = -c1[k] / w1[k];
        if (!(fabsf(v) <= 1e38f)) v = 1e38f;
        t[k] = v;
    }
#pragma unroll
    for (int p = 0; p < 8; p++) {
#pragma unroll
        for (int k = 0; k < 7; k++) {
            if ((k & 1) == (p & 1)) {
                float lo = fminf(t[k], t[k + 1]);
                float hi = fmaxf(t[k], t[k + 1]);
                t[k] = lo; t[k + 1] = hi;
            }
        }
    }

    float* dst = g_tab + (size_t)n * TAB;
    if (j == 0) {
#pragma unroll
        for (int k = 0; k < 8; k++) dst[k] = t[k];
        dst[196] = __ldg(b3 + n);
    }
    dst[188 + j] = __ldg(W3 + n * 8 + j);

#pragma unroll
    for (int s = 0; s < 9; s++) {
        float rep;
        if (s == 0)       rep = t[0] - (1.0f + 0.5f * fabsf(t[0]));
        else if (s == 8)  rep = t[7] + (1.0f + 0.5f * fabsf(t[7]));
        else              rep = 0.5f * t[s - 1] + 0.5f * t[s];

        float a = 0.0f, b = c2j;
#pragma unroll
        for (int k = 0; k < 8; k++) {
            const bool act = fmaf(w1[k], rep, c1[k]) > 0.0f;
            a = fmaf(w2r[k], act ? w1[k] : 0.0f, a);
            b = fmaf(w2r[k], act ? c1[k] : 0.0f, b);
        }
        dst[8 + s * 20 + j * 2]     = a;
        dst[8 + s * 20 + j * 2 + 1] = b;
    }
}

// ---------------- eval ----------------
// Grid: (32 o-groups, 2 batch halves, 16 i-chunks). Block 128, occ 4.
// Each CTA: 4 output cols x 8 subnets = 32 tables (25.6 KB smem).
// Each thread: 4 batch elements; x loaded once per li, reused for 4 o's.
#define O_PER_CTA 4
#define I_PER_CTA 8
#define SMEM_BYTES (O_PER_CTA * I_PER_CTA * TAB * 4)  // 25600

__device__ __forceinline__ float eval_one(
    float xe, const float* __restrict__ sb,
    const float4 tq0, const float4 tq1,
    const float4 w3a, const float4 w3b, float b3v) {
    int c = (xe > tq0.x);
    c += (xe > tq0.y); c += (xe > tq0.z); c += (xe > tq0.w);
    c += (xe > tq1.x); c += (xe > tq1.y); c += (xe > tq1.z); c += (xe > tq1.w);
    const float4* g = reinterpret_cast<const float4*>(sb + 8 + c * 20);
    const float4 p0 = g[0], p1 = g[1], p2 = g[2], p3 = g[3];
    float s = b3v;
    s = fmaf(w3a.x, fmaxf(fmaf(p0.x, xe, p0.y), 0.f), s);
    s = fmaf(w3a.y, fmaxf(fmaf(p0.z, xe, p0.w), 0.f), s);
    s = fmaf(w3a.z, fmaxf(fmaf(p1.x, xe, p1.y), 0.f), s);
    s = fmaf(w3a.w, fmaxf(fmaf(p1.z, xe, p1.w), 0.f), s);
    s = fmaf(w3b.x, fmaxf(fmaf(p2.x, xe, p2.y), 0.f), s);
    s = fmaf(w3b.y, fmaxf(fmaf(p2.z, xe, p2.w), 0.f), s);
    s = fmaf(w3b.z, fmaxf(fmaf(p3.x, xe, p3.y), 0.f), s);
    s = fmaf(w3b.w, fmaxf(fmaf(p3.z, xe, p3.w), 0.f), s);
    return s;
}

__global__ void __launch_bounds__(128, 4) eval_kernel(float* __restrict__ out) {
    extern __shared__ float sw[];
    const int obase = blockIdx.x * O_PER_CTA;
    const int bt    = blockIdx.y;
    const int ibase = blockIdx.z * I_PER_CTA;
    const int tid   = threadIdx.x;

    // Stage 32 tables, coalesced: 32 tables x 50 float4
    for (int idx = tid; idx < 32 * 50; idx += 128) {
        const int tI = idx / 50;          // table index: li*4 + lo
        const int e  = idx - tI * 50;
        const int li = tI >> 2, lo = tI & 3;
        const int n  = ((ibase + li) << 7) + obase + lo;
        reinterpret_cast<float4*>(sw)[tI * 50 + e] =
            __ldg(reinterpret_cast<const float4*>(g_tab + (size_t)n * TAB) + e);
    }
    __syncthreads();

    const int b0 = bt * 512 + tid * 4;
    float4 xv = __ldg(reinterpret_cast<const float4*>(g_xT + ibase * BATCH + b0));

    float acc[O_PER_CTA][4];
#pragma unroll
    for (int lo = 0; lo < O_PER_CTA; lo++)
#pragma unroll
        for (int e = 0; e < 4; e++) acc[lo][e] = 0.f;

    for (int li = 0; li < I_PER_CTA; li++) {
        const int inx = ibase + ((li < I_PER_CTA - 1) ? (li + 1) : li);
        const float4 xnext =
            __ldg(reinterpret_cast<const float4*>(g_xT + inx * BATCH + b0));

#pragma unroll
        for (int lo = 0; lo < O_PER_CTA; lo++) {
            const float* sb = sw + (li * 4 + lo) * TAB;
            const float4 tq0 = *reinterpret_cast<const float4*>(sb);
            const float4 tq1 = *reinterpret_cast<const float4*>(sb + 4);
            const float4 w3a = *reinterpret_cast<const float4*>(sb + 188);
            const float4 w3b = *reinterpret_cast<const float4*>(sb + 192);
            const float  b3v = sb[196];

            acc[lo][0] += eval_one(xv.x, sb, tq0, tq1, w3a, w3b, b3v);
            acc[lo][1] += eval_one(xv.y, sb, tq0, tq1, w3a, w3b, b3v);
            acc[lo][2] += eval_one(xv.z, sb, tq0, tq1, w3a, w3b, b3v);
            acc[lo][3] += eval_one(xv.w, sb, tq0, tq1, w3a, w3b, b3v);
        }
        xv = xnext;
    }

#pragma unroll
    for (int lo = 0; lo < O_PER_CTA; lo++)
#pragma unroll
        for (int e = 0; e < 4; e++)
            atomicAdd(&out[(b0 + e) * OUT_SIZE + obase + lo], acc[lo][e]);
}

extern "C" void kernel_launch(void* const* d_in, const int* in_sizes, int n_in,
                              void* d_out, int out_size) {
    const float* x  = (const float*)d_in[0];
    const float* W1 = (const float*)d_in[1];
    const float* b1 = (const float*)d_in[2];
    const float* W2 = (const float*)d_in[3];
    const float* b2 = (const float*)d_in[4];
    const float* W3 = (const float*)d_in[5];
    const float* b3 = (const float*)d_in[6];
    float* out = (float*)d_out;

    cudaFuncSetAttribute(eval_kernel, cudaFuncAttributeMaxDynamicSharedMemorySize,
                         SMEM_BYTES);

    xt_kernel<<<dim3(IN_SIZE / 32, BATCH / 32), dim3(32, 8)>>>(x);
    prep_kernel<<<N_SUB * 8 / 256, 256>>>(W1, b1, W2, b2, W3, b3, out);
    eval_kernel<<<dim3(OUT_SIZE / O_PER_CTA, 2, IN_SIZE / I_PER_CTA), 128,
                  SMEM_BYTES>>>(out);
}

// round 7
// speedup vs baseline: 1.7856x; 1.0477x over previous
#include <cuda_runtime.h>
#include <cstdint>
#include <math.h>

#define IN_SIZE  128
#define OUT_SIZE 128
#define BATCH    1024
#define N_SUB    (IN_SIZE * OUT_SIZE)

// Per-subnet table (200 floats, 800B):
//  [0..7]    sorted thresholds
//  [8+20s .. 8+20s+15]  interval s (s=0..8): 8 x (a_j, b_j)   (stride 20 = 80B
//            => distinct starting bank-quads for all intervals except c0/c8)
//  [188..195] w3   [196] b3   [197..199] pad
#define TAB 200

__device__ float g_xT[IN_SIZE * BATCH];       // transposed x
__device__ float g_tab[N_SUB * TAB];          // 13.1 MB static scratch

// ---------------- transpose x [B,128] -> xT [128,B] ----------------
__global__ void xt_kernel(const float* __restrict__ x) {
    __shared__ float t[32][33];
    const int i0 = blockIdx.x * 32;
    const int bx = blockIdx.y * 32;
    const int tx = threadIdx.x, ty = threadIdx.y;  // 32 x 8
#pragma unroll
    for (int r = 0; r < 32; r += 8)
        t[ty + r][tx] = x[(bx + ty + r) * IN_SIZE + i0 + tx];
    __syncthreads();
#pragma unroll
    for (int r = 0; r < 32; r += 8)
        g_xT[(i0 + ty + r) * BATCH + bx + tx] = t[tx][ty + r];
}

// ---------------- prep: exact per-interval linearization (8 lanes/subnet) ----
// Lane j of each 8-lane group handles hidden unit j of subnet n.
// Also zeroes the output buffer (it is poisoned before timing).
__global__ void prep_kernel(const float* __restrict__ W1, const float* __restrict__ b1,
                            const float* __restrict__ W2, const float* __restrict__ b2,
                            const float* __restrict__ W3, const float* __restrict__ b3,
                            float* __restrict__ out) {
    const int gid = blockIdx.x * 256 + threadIdx.x;      // 131072 threads
    if (gid < BATCH * OUT_SIZE / 4)                       // zero out (32768 f4)
        reinterpret_cast<float4*>(out)[gid] = make_float4(0.f, 0.f, 0.f, 0.f);

    const int n = gid >> 3;
    const int j = gid & 7;

    float w1[8], c1[8], w2r[8];
#pragma unroll
    for (int k = 0; k < 8; k++) {
        w1[k]  = __ldg(W1 + n * 8 + k);
        c1[k]  = __ldg(b1 + n * 8 + k);
        w2r[k] = __ldg(W2 + n * 64 + j * 8 + k);
    }
    const float c2j = __ldg(b2 + n * 8 + j);

    // thresholds (sentinel 1e38 for w1==0 / non-finite); sorted (redundant/lane)
    float t[8];
#pragma unroll
    for (int k = 0; k < 8; k++) {
        float v = -c1[k] / w1[k];
        if (!(fabsf(v) <= 1e38f)) v = 1e38f;
        t[k] = v;
    }
#pragma unroll
    for (int p = 0; p < 8; p++) {
#pragma unroll
        for (int k = 0; k < 7; k++) {
            if ((k & 1) == (p & 1)) {
                float lo = fminf(t[k], t[k + 1]);
                float hi = fmaxf(t[k], t[k + 1]);
                t[k] = lo; t[k + 1] = hi;
            }
        }
    }

    float* dst = g_tab + (size_t)n * TAB;
    if (j == 0) {
#pragma unroll
        for (int k = 0; k < 8; k++) dst[k] = t[k];
        dst[196] = __ldg(b3 + n);
    }
    dst[188 + j] = __ldg(W3 + n * 8 + j);

#pragma unroll
    for (int s = 0; s < 9; s++) {
        float rep;
        if (s == 0)       rep = t[0] - (1.0f + 0.5f * fabsf(t[0]));
        else if (s == 8)  rep = t[7] + (1.0f + 0.5f * fabsf(t[7]));
        else              rep = 0.5f * t[s - 1] + 0.5f * t[s];

        float a = 0.0f, b = c2j;
#pragma unroll
        for (int k = 0; k < 8; k++) {
            const bool act = fmaf(w1[k], rep, c1[k]) > 0.0f;
            a = fmaf(w2r[k], act ? w1[k] : 0.0f, a);
            b = fmaf(w2r[k], act ? c1[k] : 0.0f, b);
        }
        dst[8 + s * 20 + j * 2]     = a;
        dst[8 + s * 20 + j * 2 + 1] = b;
    }
}

// ---------------- eval ----------------
// Grid: (32 o-groups, 2 batch halves, 16 i-chunks). Block 128, occ 6
// (24 warps/SM = 6/scheduler: regs 69*128*6=53k OK, smem 25.6K*6=153.6K OK).
// Each CTA: 4 output cols x 8 subnets = 32 tables (25.6 KB smem).
// Each thread: 4 batch elements; x loaded once per li, reused for 4 o's.
#define O_PER_CTA 4
#define I_PER_CTA 8
#define SMEM_BYTES (O_PER_CTA * I_PER_CTA * TAB * 4)  // 25600

__device__ __forceinline__ float eval_one(
    float xe, const float* __restrict__ sb,
    const float4 tq0, const float4 tq1,
    const float4 w3a, const float4 w3b, float b3v) {
    int c = (xe > tq0.x);
    c += (xe > tq0.y); c += (xe > tq0.z); c += (xe > tq0.w);
    c += (xe > tq1.x); c += (xe > tq1.y); c += (xe > tq1.z); c += (xe > tq1.w);
    const float4* g = reinterpret_cast<const float4*>(sb + 8 + c * 20);
    const float4 p0 = g[0], p1 = g[1], p2 = g[2], p3 = g[3];
    float s = b3v;
    s = fmaf(w3a.x, fmaxf(fmaf(p0.x, xe, p0.y), 0.f), s);
    s = fmaf(w3a.y, fmaxf(fmaf(p0.z, xe, p0.w), 0.f), s);
    s = fmaf(w3a.z, fmaxf(fmaf(p1.x, xe, p1.y), 0.f), s);
    s = fmaf(w3a.w, fmaxf(fmaf(p1.z, xe, p1.w), 0.f), s);
    s = fmaf(w3b.x, fmaxf(fmaf(p2.x, xe, p2.y), 0.f), s);
    s = fmaf(w3b.y, fmaxf(fmaf(p2.z, xe, p2.w), 0.f), s);
    s = fmaf(w3b.z, fmaxf(fmaf(p3.x, xe, p3.y), 0.f), s);
    s = fmaf(w3b.w, fmaxf(fmaf(p3.z, xe, p3.w), 0.f), s);
    return s;
}

__global__ void __launch_bounds__(128, 6) eval_kernel(float* __restrict__ out) {
    extern __shared__ float sw[];
    const int obase = blockIdx.x * O_PER_CTA;
    const int bt    = blockIdx.y;
    const int ibase = blockIdx.z * I_PER_CTA;
    const int tid   = threadIdx.x;

    // Stage 32 tables, coalesced: 32 tables x 50 float4
    for (int idx = tid; idx < 32 * 50; idx += 128) {
        const int tI = idx / 50;          // table index: li*4 + lo
        const int e  = idx - tI * 50;
        const int li = tI >> 2, lo = tI & 3;
        const int n  = ((ibase + li) << 7) + obase + lo;
        reinterpret_cast<float4*>(sw)[tI * 50 + e] =
            __ldg(reinterpret_cast<const float4*>(g_tab + (size_t)n * TAB) + e);
    }
    __syncthreads();

    const int b0 = bt * 512 + tid * 4;
    float4 xv = __ldg(reinterpret_cast<const float4*>(g_xT + ibase * BATCH + b0));

    float acc[O_PER_CTA][4];
#pragma unroll
    for (int lo = 0; lo < O_PER_CTA; lo++)
#pragma unroll
        for (int e = 0; e < 4; e++) acc[lo][e] = 0.f;

    for (int li = 0; li < I_PER_CTA; li++) {
        const int inx = ibase + ((li < I_PER_CTA - 1) ? (li + 1) : li);
        const float4 xnext =
            __ldg(reinterpret_cast<const float4*>(g_xT + inx * BATCH + b0));

#pragma unroll
        for (int lo = 0; lo < O_PER_CTA; lo++) {
            const float* sb = sw + (li * 4 + lo) * TAB;
            const float4 tq0 = *reinterpret_cast<const float4*>(sb);
            const float4 tq1 = *reinterpret_cast<const float4*>(sb + 4);
            const float4 w3a = *reinterpret_cast<const float4*>(sb + 188);
            const float4 w3b = *reinterpret_cast<const float4*>(sb + 192);
            const float  b3v = sb[196];

            acc[lo][0] += eval_one(xv.x, sb, tq0, tq1, w3a, w3b, b3v);
            acc[lo][1] += eval_one(xv.y, sb, tq0, tq1, w3a, w3b, b3v);
            acc[lo][2] += eval_one(xv.z, sb, tq0, tq1, w3a, w3b, b3v);
            acc[lo][3] += eval_one(xv.w, sb, tq0, tq1, w3a, w3b, b3v);
        }
        xv = xnext;
    }

#pragma unroll
    for (int lo = 0; lo < O_PER_CTA; lo++)
#pragma unroll
        for (int e = 0; e < 4; e++)
            atomicAdd(&out[(b0 + e) * OUT_SIZE + obase + lo], acc[lo][e]);
}

extern "C" void kernel_launch(void* const* d_in, const int* in_sizes, int n_in,
                              void* d_out, int out_size) {
    const float* x  = (const float*)d_in[0];
    const float* W1 = (const float*)d_in[1];
    const float* b1 = (const float*)d_in[2];
    const float* W2 = (const float*)d_in[3];
    const float* b2 = (const float*)d_in[4];
    const float* W3 = (const float*)d_in[5];
    const float* b3 = (const float*)d_in[6];
    float* out = (float*)d_out;

    cudaFuncSetAttribute(eval_kernel, cudaFuncAttributeMaxDynamicSharedMemorySize,
                         SMEM_BYTES);

    xt_kernel<<<dim3(IN_SIZE / 32, BATCH / 32), dim3(32, 8)>>>(x);
    prep_kernel<<<N_SUB * 8 / 256, 256>>>(W1, b1, W2, b2, W3, b3, out);
    eval_kernel<<<dim3(OUT_SIZE / O_PER_CTA, 2, IN_SIZE / I_PER_CTA), 128,
                  SMEM_BYTES>>>(out);
}